// round 5
// baseline (speedup 1.0000x reference)
#include <cuda_runtime.h>
#include <cuda_bf16.h>
#include <cstdint>

#define NNODES 8192
#define DIM    512
#define NLAYER 2
#define SLOPE  0.01f

// ---------------------------------------------------------------------------
// Scratch (device globals; allocation-free per harness rules)
// ---------------------------------------------------------------------------
__device__ __align__(256) float g_scores[(size_t)NNODES * NNODES];   // 256 MB
__device__ __align__(256) float g_xbuf[NNODES * DIM];                // 16 MB
__device__ __align__(256) __nv_bfloat16 g_projh[NNODES * 2 * DIM];
__device__ __align__(256) __nv_bfloat16 g_projl[NNODES * 2 * DIM];
__device__ __align__(256) __nv_bfloat16 g_sh[(size_t)NNODES * NNODES]; // 128 MB
__device__ __align__(256) __nv_bfloat16 g_sl[(size_t)NNODES * NNODES]; // 128 MB
__device__ __align__(256) __nv_bfloat16 g_whTh[DIM * NNODES];
__device__ __align__(256) __nv_bfloat16 g_whTl[DIM * NNODES];
__device__ __align__(256) __nv_bfloat16 g_xh[NNODES * DIM];
__device__ __align__(256) __nv_bfloat16 g_xl[NNODES * DIM];
__device__ __align__(256) __nv_bfloat16 g_wth[2 * DIM * DIM];
__device__ __align__(256) __nv_bfloat16 g_wtl[2 * DIM * DIM];

// ---------------------------------------------------------------------------
// Portable PTX helpers (valid on base compute_103 target)
// ---------------------------------------------------------------------------
__device__ __forceinline__ uint32_t smem_u32(const void* p) {
    uint32_t a;
    asm("{ .reg .u64 t; cvta.to.shared.u64 t, %1; cvt.u32.u64 %0, t; }" : "=r"(a) : "l"(p));
    return a;
}
__device__ __forceinline__ uint32_t swz(uint32_t off) {
    return off ^ ((off >> 3) & 0x70);
}
__device__ __forceinline__ void cp16(uint32_t dst, const void* src) {
    asm volatile("cp.async.cg.shared.global [%0], [%1], 16;" :: "r"(dst), "l"(src));
}
__device__ __forceinline__ void ldm4(uint32_t addr, uint32_t r[4]) {
    asm volatile("ldmatrix.sync.aligned.m8n8.x4.shared.b16 {%0,%1,%2,%3}, [%4];"
                 : "=r"(r[0]), "=r"(r[1]), "=r"(r[2]), "=r"(r[3]) : "r"(addr));
}
__device__ __forceinline__ void mma_bf16(float* c, const uint32_t a[4],
                                         uint32_t b0, uint32_t b1) {
    asm volatile(
        "mma.sync.aligned.m16n8k16.row.col.f32.bf16.bf16.f32 "
        "{%0,%1,%2,%3}, {%4,%5,%6,%7}, {%8,%9}, {%0,%1,%2,%3};"
        : "+f"(c[0]), "+f"(c[1]), "+f"(c[2]), "+f"(c[3])
        : "r"(a[0]), "r"(a[1]), "r"(a[2]), "r"(a[3]), "r"(b0), "r"(b1));
}

// ---------------------------------------------------------------------------
// Split-bf16 HMMA GEMM: C[M,N](fp32) = (Ah+Al)[M,K] @ (Bh+Bl)[N,K]^T
// (drops Al*Bl). CTA tile 128x128, BK=32, cp.async double buffer.
// 8 warps, warp tile 64x32.
// MODE 0: C fp32.  MODE 1: C = leaky_relu(acc + resid) fp32.
// MODE 2: C written as split bf16 pair (Ch, Cl).
// ---------------------------------------------------------------------------
#define STAGE_BYTES 32768            // Ah 8K | Al 8K | Bh 8K | Bl 8K
#define GEMM_SMEM   (2 * STAGE_BYTES)

template <int MODE>
__global__ __launch_bounds__(256, 2)
void gemm_mma(const __nv_bfloat16* __restrict__ Ah, const __nv_bfloat16* __restrict__ Al,
              int lda,
              const __nv_bfloat16* __restrict__ Bh, const __nv_bfloat16* __restrict__ Bl,
              int ldb,
              float* __restrict__ C,
              __nv_bfloat16* __restrict__ Ch, __nv_bfloat16* __restrict__ Cl,
              int ldc,
              const float* __restrict__ resid, int ldr, int K)
{
    extern __shared__ __align__(1024) char smch[];
    const uint32_t smb = smem_u32(smch);
    const int tid  = threadIdx.x;
    const int lane = tid & 31;
    const int wid  = tid >> 5;
    const int wm   = wid >> 2;      // 0..1  -> 64-row slab
    const int wn   = wid & 3;       // 0..3  -> 32-col slab
    const int bm = blockIdx.y * 128;
    const int bn = blockIdx.x * 128;

    const __nv_bfloat16* srcs[4] = {
        Ah + (size_t)bm * lda, Al + (size_t)bm * lda,
        Bh + (size_t)bn * ldb, Bl + (size_t)bn * ldb };

    // cp.async tile mapping: per array, 512 16B chunks; thread does 2.
    const int row0 = tid >> 2;             // rows tid/4 and 64 + tid/4
    const int seg  = tid & 3;              // 16B segment (8 bf16)
    const uint32_t soff0 = swz((row0 << 6) | (seg << 4));
    const uint32_t soff1 = swz(((row0 + 64) << 6) | (seg << 4));

    float acc[4][4][4];
    #pragma unroll
    for (int i = 0; i < 4; ++i)
        #pragma unroll
        for (int j = 0; j < 4; ++j)
            #pragma unroll
            for (int k = 0; k < 4; ++k) acc[i][j][k] = 0.f;

    // ldmatrix per-lane base byte offsets (unswizzled)
    const uint32_t a_base =
        (uint32_t)((wm * 64 + (lane & 15)) << 6) + ((lane >> 4) << 4);
    const uint32_t b_base =
        (uint32_t)((wn * 32 + (lane & 7) + ((lane >> 4) << 3)) << 6) + (((lane >> 3) & 1) << 4);

    const int T = K >> 5;   // BK=32 chunks

    auto load_stage = [&](int stg, int kt) {
        const uint32_t sb = smb + stg * STAGE_BYTES;
        #pragma unroll
        for (int h = 0; h < 4; ++h) {
            const int ld = (h < 2) ? lda : ldb;
            const __nv_bfloat16* base = srcs[h] + kt + seg * 8;
            cp16(sb + h * 8192 + soff0, base + (size_t)row0 * ld);
            cp16(sb + h * 8192 + soff1, base + (size_t)(row0 + 64) * ld);
        }
        asm volatile("cp.async.commit_group;");
    };

    load_stage(0, 0);

    for (int t = 0; t < T; ++t) {
        if (t + 1 < T) {
            load_stage((t + 1) & 1, (t + 1) << 5);
            asm volatile("cp.async.wait_group 1;");
        } else {
            asm volatile("cp.async.wait_group 0;");
        }
        __syncthreads();

        const uint32_t sb = smb + (t & 1) * STAGE_BYTES;
        #pragma unroll
        for (int kk = 0; kk < 2; ++kk) {          // two k16 steps
            const uint32_t kb = kk * 32;
            uint32_t af[4][4], bhf[2][4], blf[2][4];
            #pragma unroll
            for (int i = 0; i < 4; ++i)
                ldm4(sb + swz(a_base + i * 1024 + kb), af[i]);
            #pragma unroll
            for (int p = 0; p < 2; ++p)
                ldm4(sb + 16384 + swz(b_base + p * 1024 + kb), bhf[p]);
            #pragma unroll
            for (int p = 0; p < 2; ++p)
                ldm4(sb + 24576 + swz(b_base + p * 1024 + kb), blf[p]);

            // Ah*Bh
            #pragma unroll
            for (int i = 0; i < 4; ++i)
                #pragma unroll
                for (int p = 0; p < 2; ++p) {
                    mma_bf16(acc[i][2 * p + 0], af[i], bhf[p][0], bhf[p][1]);
                    mma_bf16(acc[i][2 * p + 1], af[i], bhf[p][2], bhf[p][3]);
                }
            // Ah*Bl
            #pragma unroll
            for (int i = 0; i < 4; ++i)
                #pragma unroll
                for (int p = 0; p < 2; ++p) {
                    mma_bf16(acc[i][2 * p + 0], af[i], blf[p][0], blf[p][1]);
                    mma_bf16(acc[i][2 * p + 1], af[i], blf[p][2], blf[p][3]);
                }
            // Al (overwrite af) * Bh
            #pragma unroll
            for (int i = 0; i < 4; ++i)
                ldm4(sb + 8192 + swz(a_base + i * 1024 + kb), af[i]);
            #pragma unroll
            for (int i = 0; i < 4; ++i)
                #pragma unroll
                for (int p = 0; p < 2; ++p) {
                    mma_bf16(acc[i][2 * p + 0], af[i], bhf[p][0], bhf[p][1]);
                    mma_bf16(acc[i][2 * p + 1], af[i], bhf[p][2], bhf[p][3]);
                }
        }
        __syncthreads();
    }

    // ---- epilogue ----
    #pragma unroll
    for (int i = 0; i < 4; ++i) {
        const int r0 = bm + wm * 64 + i * 16 + (lane >> 2);
        #pragma unroll
        for (int j = 0; j < 4; ++j) {
            const int col = bn + wn * 32 + j * 8 + (lane & 3) * 2;
            float v0 = acc[i][j][0], v1 = acc[i][j][1];
            float v2 = acc[i][j][2], v3 = acc[i][j][3];
            if (MODE == 1) {
                const float* rp0 = resid + (size_t)r0 * ldr + col;
                const float* rp1 = resid + (size_t)(r0 + 8) * ldr + col;
                v0 += rp0[0]; v1 += rp0[1];
                v2 += rp1[0]; v3 += rp1[1];
                v0 = v0 >= 0.f ? v0 : SLOPE * v0;
                v1 = v1 >= 0.f ? v1 : SLOPE * v1;
                v2 = v2 >= 0.f ? v2 : SLOPE * v2;
                v3 = v3 >= 0.f ? v3 : SLOPE * v3;
            }
            if (MODE == 2) {
                __nv_bfloat16 h0 = __float2bfloat16_rn(v0);
                __nv_bfloat16 h1 = __float2bfloat16_rn(v1);
                __nv_bfloat16 h2 = __float2bfloat16_rn(v2);
                __nv_bfloat16 h3 = __float2bfloat16_rn(v3);
                *(__nv_bfloat162*)(Ch + (size_t)r0 * ldc + col) = __nv_bfloat162(h0, h1);
                *(__nv_bfloat162*)(Ch + (size_t)(r0 + 8) * ldc + col) = __nv_bfloat162(h2, h3);
                *(__nv_bfloat162*)(Cl + (size_t)r0 * ldc + col) =
                    __nv_bfloat162(__float2bfloat16_rn(v0 - __bfloat162float(h0)),
                                   __float2bfloat16_rn(v1 - __bfloat162float(h1)));
                *(__nv_bfloat162*)(Cl + (size_t)(r0 + 8) * ldc + col) =
                    __nv_bfloat162(__float2bfloat16_rn(v2 - __bfloat162float(h2)),
                                   __float2bfloat16_rn(v3 - __bfloat162float(h3)));
            } else {
                *(float2*)(C + (size_t)r0 * ldc + col)       = make_float2(v0, v1);
                *(float2*)(C + (size_t)(r0 + 8) * ldc + col) = make_float2(v2, v3);
            }
        }
    }
}

// ---------------------------------------------------------------------------
// fp32 -> (hi, lo) bf16, same layout (flat, vectorized by 4)
// ---------------------------------------------------------------------------
__global__ void split_rows_kernel(const float* __restrict__ in,
                                  __nv_bfloat16* __restrict__ h,
                                  __nv_bfloat16* __restrict__ l, size_t n4)
{
    size_t i = (size_t)blockIdx.x * blockDim.x + threadIdx.x;
    if (i >= n4) return;
    float4 v = ((const float4*)in)[i];
    __nv_bfloat16 hx = __float2bfloat16_rn(v.x);
    __nv_bfloat16 hy = __float2bfloat16_rn(v.y);
    __nv_bfloat16 hz = __float2bfloat16_rn(v.z);
    __nv_bfloat16 hw = __float2bfloat16_rn(v.w);
    __nv_bfloat162* h2 = (__nv_bfloat162*)h;
    __nv_bfloat162* l2 = (__nv_bfloat162*)l;
    h2[2 * i + 0] = __nv_bfloat162(hx, hy);
    h2[2 * i + 1] = __nv_bfloat162(hz, hw);
    l2[2 * i + 0] = __nv_bfloat162(__float2bfloat16_rn(v.x - __bfloat162float(hx)),
                                   __float2bfloat16_rn(v.y - __bfloat162float(hy)));
    l2[2 * i + 1] = __nv_bfloat162(__float2bfloat16_rn(v.z - __bfloat162float(hz)),
                                   __float2bfloat16_rn(v.w - __bfloat162float(hw)));
}

// ---------------------------------------------------------------------------
// fp32 [R x C] (ld=ldin) -> transposed (hi, lo) bf16 [C x R]  (weights only)
// ---------------------------------------------------------------------------
__global__ void splitT_kernel(const float* __restrict__ in, int ldin, int R,
                              __nv_bfloat16* __restrict__ h, __nv_bfloat16* __restrict__ l)
{
    __shared__ float t[32][33];
    const int c0 = blockIdx.x * 32, r0 = blockIdx.y * 32;
    #pragma unroll
    for (int j = 0; j < 4; ++j) {
        int r = r0 + threadIdx.y + j * 8;
        t[threadIdx.y + j * 8][threadIdx.x] = in[(size_t)r * ldin + c0 + threadIdx.x];
    }
    __syncthreads();
    #pragma unroll
    for (int j = 0; j < 4; ++j) {
        int c = c0 + threadIdx.y + j * 8;
        float v = t[threadIdx.x][threadIdx.y + j * 8];
        __nv_bfloat16 hv = __float2bfloat16_rn(v);
        h[(size_t)c * R + r0 + threadIdx.x] = hv;
        l[(size_t)c * R + r0 + threadIdx.x] =
            __float2bfloat16_rn(v - __bfloat162float(hv));
    }
}

// ---------------------------------------------------------------------------
// bf16-pair transpose: (h,l)[R x Cin] cols [0,Cout) -> (h,l)T [Cout x R]
// Exact: hi/lo of the transposed value equal the transposed hi/lo.
// ---------------------------------------------------------------------------
__global__ void transpose_pair_kernel(const __nv_bfloat16* __restrict__ hin,
                                      const __nv_bfloat16* __restrict__ lin, int ldin,
                                      __nv_bfloat16* __restrict__ hout,
                                      __nv_bfloat16* __restrict__ lout, int ldout)
{
    __shared__ __nv_bfloat16 th[32][34];
    __shared__ __nv_bfloat16 tl[32][34];
    const int r0 = blockIdx.x * 32, c0 = blockIdx.y * 32;
    #pragma unroll
    for (int j = 0; j < 4; ++j) {
        int r = r0 + threadIdx.y + j * 8;
        th[threadIdx.y + j * 8][threadIdx.x] = hin[(size_t)r * ldin + c0 + threadIdx.x];
        tl[threadIdx.y + j * 8][threadIdx.x] = lin[(size_t)r * ldin + c0 + threadIdx.x];
    }
    __syncthreads();
    #pragma unroll
    for (int j = 0; j < 4; ++j) {
        int c = c0 + threadIdx.y + j * 8;
        hout[(size_t)c * ldout + r0 + threadIdx.x] = th[threadIdx.x][threadIdx.y + j * 8];
        lout[(size_t)c * ldout + r0 + threadIdx.x] = tl[threadIdx.x][threadIdx.y + j * 8];
    }
}

// ---------------------------------------------------------------------------
// Row softmax * adj, emitting split bf16 (hi, lo). One 512-thread block / row.
// ---------------------------------------------------------------------------
__global__ void softmax_mask_split_kernel(const float* __restrict__ S,
                                          const float* __restrict__ adj,
                                          __nv_bfloat16* __restrict__ sh,
                                          __nv_bfloat16* __restrict__ sl)
{
    __shared__ float red[16];
    const int row = blockIdx.x;
    const int tid = threadIdx.x;
    const float4* srow = (const float4*)(S + (size_t)row * NNODES);
    const float4* arow = (const float4*)(adj + (size_t)row * NNODES);

    float4 v[4];
    float m = -3.4e38f;
    #pragma unroll
    for (int i = 0; i < 4; ++i) {
        v[i] = srow[tid + i * 512];
        m = fmaxf(m, fmaxf(fmaxf(v[i].x, v[i].y), fmaxf(v[i].z, v[i].w)));
    }
    #pragma unroll
    for (int o = 16; o > 0; o >>= 1) m = fmaxf(m, __shfl_xor_sync(~0u, m, o));
    if ((tid & 31) == 0) red[tid >> 5] = m;
    __syncthreads();
    m = red[0];
    #pragma unroll
    for (int i = 1; i < 16; ++i) m = fmaxf(m, red[i]);
    __syncthreads();

    float s = 0.f;
    #pragma unroll
    for (int i = 0; i < 4; ++i) {
        v[i].x = __expf(v[i].x - m); v[i].y = __expf(v[i].y - m);
        v[i].z = __expf(v[i].z - m); v[i].w = __expf(v[i].w - m);
        s += (v[i].x + v[i].y) + (v[i].z + v[i].w);
    }
    #pragma unroll
    for (int o = 16; o > 0; o >>= 1) s += __shfl_xor_sync(~0u, s, o);
    if ((tid & 31) == 0) red[tid >> 5] = s;
    __syncthreads();
    s = red[0];
    #pragma unroll
    for (int i = 1; i < 16; ++i) s += red[i];

    const float inv = 1.0f / s;
    __nv_bfloat162* h2 = (__nv_bfloat162*)(sh + (size_t)row * NNODES);
    __nv_bfloat162* l2 = (__nv_bfloat162*)(sl + (size_t)row * NNODES);
    #pragma unroll
    for (int i = 0; i < 4; ++i) {
        float4 a = arow[tid + i * 512];
        float4 p;
        p.x = v[i].x * inv * a.x; p.y = v[i].y * inv * a.y;
        p.z = v[i].z * inv * a.z; p.w = v[i].w * inv * a.w;
        __nv_bfloat16 hx = __float2bfloat16_rn(p.x);
        __nv_bfloat16 hy = __float2bfloat16_rn(p.y);
        __nv_bfloat16 hz = __float2bfloat16_rn(p.z);
        __nv_bfloat16 hw = __float2bfloat16_rn(p.w);
        int idx = tid + i * 512;
        h2[2 * idx + 0] = __nv_bfloat162(hx, hy);
        h2[2 * idx + 1] = __nv_bfloat162(hz, hw);
        l2[2 * idx + 0] = __nv_bfloat162(__float2bfloat16_rn(p.x - __bfloat162float(hx)),
                                         __float2bfloat16_rn(p.y - __bfloat162float(hy)));
        l2[2 * idx + 1] = __nv_bfloat162(__float2bfloat16_rn(p.z - __bfloat162float(hz)),
                                         __float2bfloat16_rn(p.w - __bfloat162float(hw)));
    }
}

// ---------------------------------------------------------------------------
extern "C" void kernel_launch(void* const* d_in, const int* in_sizes, int n_in,
                              void* d_out, int out_size)
{
    const float* x0  = (const float*)d_in[0];  // [8192, 512]
    const float* adj = (const float*)d_in[1];  // [8192, 8192]
    const float* Wst = (const float*)d_in[2];  // [2, 512, 1024]
    float* out = (float*)d_out;

    cudaFuncSetAttribute(gemm_mma<0>, cudaFuncAttributeMaxDynamicSharedMemorySize, GEMM_SMEM);
    cudaFuncSetAttribute(gemm_mma<1>, cudaFuncAttributeMaxDynamicSharedMemorySize, GEMM_SMEM);
    cudaFuncSetAttribute(gemm_mma<2>, cudaFuncAttributeMaxDynamicSharedMemorySize, GEMM_SMEM);

    float *scores, *xbuf;
    __nv_bfloat16 *projh, *projl, *sh, *sl, *whTh, *whTl, *xh, *xl, *wth, *wtl;
    cudaGetSymbolAddress((void**)&scores, g_scores);
    cudaGetSymbolAddress((void**)&xbuf,   g_xbuf);
    cudaGetSymbolAddress((void**)&projh,  g_projh);
    cudaGetSymbolAddress((void**)&projl,  g_projl);
    cudaGetSymbolAddress((void**)&sh,     g_sh);
    cudaGetSymbolAddress((void**)&sl,     g_sl);
    cudaGetSymbolAddress((void**)&whTh,   g_whTh);
    cudaGetSymbolAddress((void**)&whTl,   g_whTl);
    cudaGetSymbolAddress((void**)&xh,     g_xh);
    cudaGetSymbolAddress((void**)&xl,     g_xl);
    cudaGetSymbolAddress((void**)&wth,    g_wth);
    cudaGetSymbolAddress((void**)&wtl,    g_wtl);

    for (int l = 0; l < NLAYER; ++l) {
        const float* xin  = l ? xbuf : x0;
        float*       xout = l ? out  : xbuf;
        const float* W = Wst + (size_t)l * DIM * (2 * DIM);

        // x -> split bf16
        {
            size_t n4 = (size_t)NNODES * DIM / 4;
            split_rows_kernel<<<(unsigned)((n4 + 255) / 256), 256>>>(xin, xh, xl, n4);
        }
        // W -> transposed split bf16
        splitT_kernel<<<dim3(2 * DIM / 32, DIM / 32), dim3(32, 8)>>>(W, 2 * DIM, DIM, wth, wtl);

        // G1: proj = x @ W, written directly as split bf16 pair
        gemm_mma<2><<<dim3(2 * DIM / 128, NNODES / 128), 256, GEMM_SMEM>>>(
            xh, xl, DIM, wth, wtl, DIM,
            nullptr, projh, projl, 2 * DIM, nullptr, 0, DIM);

        // Wh^T pair for the AV gemm B operand [512, 8192]
        transpose_pair_kernel<<<dim3(NNODES / 32, DIM / 32), dim3(32, 8)>>>(
            projh, projl, 2 * DIM, whTh, whTl, NNODES);

        // G2: scores = Wh @ Ws^T (fp32 out)
        gemm_mma<0><<<dim3(NNODES / 128, NNODES / 128), 256, GEMM_SMEM>>>(
            projh, projl, 2 * DIM, projh + DIM, projl + DIM, 2 * DIM,
            scores, nullptr, nullptr, NNODES, nullptr, 0, DIM);

        // softmax * adj -> split bf16
        softmax_mask_split_kernel<<<NNODES, 512>>>(scores, adj, sh, sl);

        // G3: xout = leaky(S @ Wh + xin)
        gemm_mma<1><<<dim3(DIM / 128, NNODES / 128), 256, GEMM_SMEM>>>(
            sh, sl, NNODES, whTh, whTl, NNODES,
            xout, nullptr, nullptr, DIM, xin, DIM, NNODES);
    }
}

// round 8
// speedup vs baseline: 1.0123x; 1.0123x over previous
#include <cuda_runtime.h>
#include <cuda_bf16.h>
#include <cstdint>

#define NNODES 8192
#define DIM    512
#define NLAYER 2
#define SLOPE  0.01f

// ---------------------------------------------------------------------------
// Scratch (device globals; allocation-free per harness rules)
// ---------------------------------------------------------------------------
__device__ __align__(256) float g_scores[(size_t)NNODES * NNODES];   // 256 MB
__device__ __align__(256) float g_xbuf[NNODES * DIM];                // 16 MB
__device__ __align__(256) __nv_bfloat16 g_projh[NNODES * 2 * DIM];
__device__ __align__(256) __nv_bfloat16 g_projl[NNODES * 2 * DIM];
__device__ __align__(256) __nv_bfloat16 g_sh[(size_t)NNODES * NNODES]; // 128 MB
__device__ __align__(256) __nv_bfloat16 g_sl[(size_t)NNODES * NNODES]; // 128 MB
__device__ __align__(256) __nv_bfloat16 g_whTh[DIM * NNODES];
__device__ __align__(256) __nv_bfloat16 g_whTl[DIM * NNODES];
__device__ __align__(256) __nv_bfloat16 g_xh[NNODES * DIM];
__device__ __align__(256) __nv_bfloat16 g_xl[NNODES * DIM];
__device__ __align__(256) __nv_bfloat16 g_wth[2 * DIM * DIM];
__device__ __align__(256) __nv_bfloat16 g_wtl[2 * DIM * DIM];

// ---------------------------------------------------------------------------
// Portable PTX helpers (valid on base compute_103 target)
// ---------------------------------------------------------------------------
__device__ __forceinline__ uint32_t smem_u32(const void* p) {
    uint32_t a;
    asm("{ .reg .u64 t; cvta.to.shared.u64 t, %1; cvt.u32.u64 %0, t; }" : "=r"(a) : "l"(p));
    return a;
}
__device__ __forceinline__ uint32_t swz(uint32_t off) {
    return off ^ ((off >> 3) & 0x70);
}
__device__ __forceinline__ void cp16(uint32_t dst, const void* src) {
    asm volatile("cp.async.cg.shared.global [%0], [%1], 16;" :: "r"(dst), "l"(src));
}
__device__ __forceinline__ void ldm4(uint32_t addr, uint32_t r[4]) {
    asm volatile("ldmatrix.sync.aligned.m8n8.x4.shared.b16 {%0,%1,%2,%3}, [%4];"
                 : "=r"(r[0]), "=r"(r[1]), "=r"(r[2]), "=r"(r[3]) : "r"(addr));
}
__device__ __forceinline__ void mma_bf16(float* c, const uint32_t a[4],
                                         uint32_t b0, uint32_t b1) {
    asm volatile(
        "mma.sync.aligned.m16n8k16.row.col.f32.bf16.bf16.f32 "
        "{%0,%1,%2,%3}, {%4,%5,%6,%7}, {%8,%9}, {%0,%1,%2,%3};"
        : "+f"(c[0]), "+f"(c[1]), "+f"(c[2]), "+f"(c[3])
        : "r"(a[0]), "r"(a[1]), "r"(a[2]), "r"(a[3]), "r"(b0), "r"(b1));
}

// ---------------------------------------------------------------------------
// Split-bf16 HMMA GEMM: C[M,N](fp32) = (Ah+Al)[M,K] @ (Bh+Bl)[N,K]^T
// (drops Al*Bl). CTA tile 128x128, BK=32, cp.async double buffer.
// 128 threads, 4 warps in 2x2 grid, warp tile 64x64 (halves LDSM/HMMA ratio).
// MODE 0: C fp32.  MODE 1: C = leaky_relu(acc + resid) fp32.
// MODE 2: C written as split bf16 pair (Ch, Cl).
// ---------------------------------------------------------------------------
#define STAGE_BYTES 32768            // Ah 8K | Al 8K | Bh 8K | Bl 8K
#define GEMM_SMEM   (2 * STAGE_BYTES)

template <int MODE>
__global__ __launch_bounds__(128, 2)
void gemm_mma(const __nv_bfloat16* __restrict__ Ah, const __nv_bfloat16* __restrict__ Al,
              int lda,
              const __nv_bfloat16* __restrict__ Bh, const __nv_bfloat16* __restrict__ Bl,
              int ldb,
              float* __restrict__ C,
              __nv_bfloat16* __restrict__ Ch, __nv_bfloat16* __restrict__ Cl,
              int ldc,
              const float* __restrict__ resid, int ldr, int K)
{
    extern __shared__ __align__(1024) char smch[];
    const uint32_t smb = smem_u32(smch);
    const int tid  = threadIdx.x;
    const int lane = tid & 31;
    const int wid  = tid >> 5;
    const int wm   = wid >> 1;      // 0..1 -> 64-row slab
    const int wn   = wid & 1;       // 0..1 -> 64-col slab
    const int bm = blockIdx.y * 128;
    const int bn = blockIdx.x * 128;

    const __nv_bfloat16* srcs[4] = {
        Ah + (size_t)bm * lda, Al + (size_t)bm * lda,
        Bh + (size_t)bn * ldb, Bl + (size_t)bn * ldb };

    // cp.async: per array 512 16B chunks; 128 threads -> 4 per thread per array
    const int row0 = tid >> 2;             // 0..31
    const int seg  = tid & 3;              // 16B segment (8 bf16)
    uint32_t soff[4];
    #pragma unroll
    for (int j = 0; j < 4; ++j)
        soff[j] = swz((uint32_t)(((row0 + j * 32) << 6) | (seg << 4)));

    float acc[4][8][4];
    #pragma unroll
    for (int i = 0; i < 4; ++i)
        #pragma unroll
        for (int j = 0; j < 8; ++j)
            #pragma unroll
            for (int k = 0; k < 4; ++k) acc[i][j][k] = 0.f;

    // ldmatrix per-lane base byte offsets (unswizzled)
    const uint32_t a_base =
        (uint32_t)((wm * 64 + (lane & 15)) << 6) + ((lane >> 4) << 4);
    const uint32_t b_base =
        (uint32_t)((wn * 64 + (lane & 7) + ((lane >> 4) << 3)) << 6) + (((lane >> 3) & 1) << 4);

    const int T = K >> 5;   // BK=32 chunks

    auto load_stage = [&](int stg, int kt) {
        const uint32_t sb = smb + stg * STAGE_BYTES;
        #pragma unroll
        for (int h = 0; h < 4; ++h) {
            const int ld = (h < 2) ? lda : ldb;
            const __nv_bfloat16* base = srcs[h] + kt + seg * 8;
            #pragma unroll
            for (int j = 0; j < 4; ++j)
                cp16(sb + h * 8192 + soff[j], base + (size_t)(row0 + j * 32) * ld);
        }
        asm volatile("cp.async.commit_group;");
    };

    load_stage(0, 0);

    for (int t = 0; t < T; ++t) {
        if (t + 1 < T) {
            load_stage((t + 1) & 1, (t + 1) << 5);
            asm volatile("cp.async.wait_group 1;");
        } else {
            asm volatile("cp.async.wait_group 0;");
        }
        __syncthreads();

        const uint32_t sb = smb + (t & 1) * STAGE_BYTES;
        #pragma unroll
        for (int kk = 0; kk < 2; ++kk) {          // two k16 steps
            const uint32_t kb = kk * 32;
            uint32_t bh[4][4], bl[4][4], af[4][4];
            #pragma unroll
            for (int p = 0; p < 4; ++p)
                ldm4(sb + 16384 + swz(b_base + p * 1024 + kb), bh[p]);
            #pragma unroll
            for (int p = 0; p < 4; ++p)
                ldm4(sb + 24576 + swz(b_base + p * 1024 + kb), bl[p]);
            #pragma unroll
            for (int i = 0; i < 4; ++i)
                ldm4(sb + swz(a_base + i * 1024 + kb), af[i]);

            // Ah*Bh
            #pragma unroll
            for (int i = 0; i < 4; ++i)
                #pragma unroll
                for (int p = 0; p < 4; ++p) {
                    mma_bf16(acc[i][2 * p + 0], af[i], bh[p][0], bh[p][1]);
                    mma_bf16(acc[i][2 * p + 1], af[i], bh[p][2], bh[p][3]);
                }
            // Ah*Bl
            #pragma unroll
            for (int i = 0; i < 4; ++i)
                #pragma unroll
                for (int p = 0; p < 4; ++p) {
                    mma_bf16(acc[i][2 * p + 0], af[i], bl[p][0], bl[p][1]);
                    mma_bf16(acc[i][2 * p + 1], af[i], bl[p][2], bl[p][3]);
                }
            // Al (overwrite af) * Bh
            #pragma unroll
            for (int i = 0; i < 4; ++i)
                ldm4(sb + 8192 + swz(a_base + i * 1024 + kb), af[i]);
            #pragma unroll
            for (int i = 0; i < 4; ++i)
                #pragma unroll
                for (int p = 0; p < 4; ++p) {
                    mma_bf16(acc[i][2 * p + 0], af[i], bh[p][0], bh[p][1]);
                    mma_bf16(acc[i][2 * p + 1], af[i], bh[p][2], bh[p][3]);
                }
        }
        __syncthreads();
    }

    // ---- epilogue ----
    #pragma unroll
    for (int i = 0; i < 4; ++i) {
        const int r0 = bm + wm * 64 + i * 16 + (lane >> 2);
        #pragma unroll
        for (int j = 0; j < 8; ++j) {
            const int col = bn + wn * 64 + j * 8 + (lane & 3) * 2;
            float v0 = acc[i][j][0], v1 = acc[i][j][1];
            float v2 = acc[i][j][2], v3 = acc[i][j][3];
            if (MODE == 1) {
                const float* rp0 = resid + (size_t)r0 * ldr + col;
                const float* rp1 = resid + (size_t)(r0 + 8) * ldr + col;
                v0 += rp0[0]; v1 += rp0[1];
                v2 += rp1[0]; v3 += rp1[1];
                v0 = v0 >= 0.f ? v0 : SLOPE * v0;
                v1 = v1 >= 0.f ? v1 : SLOPE * v1;
                v2 = v2 >= 0.f ? v2 : SLOPE * v2;
                v3 = v3 >= 0.f ? v3 : SLOPE * v3;
            }
            if (MODE == 2) {
                __nv_bfloat16 h0 = __float2bfloat16_rn(v0);
                __nv_bfloat16 h1 = __float2bfloat16_rn(v1);
                __nv_bfloat16 h2 = __float2bfloat16_rn(v2);
                __nv_bfloat16 h3 = __float2bfloat16_rn(v3);
                *(__nv_bfloat162*)(Ch + (size_t)r0 * ldc + col) = __nv_bfloat162(h0, h1);
                *(__nv_bfloat162*)(Ch + (size_t)(r0 + 8) * ldc + col) = __nv_bfloat162(h2, h3);
                *(__nv_bfloat162*)(Cl + (size_t)r0 * ldc + col) =
                    __nv_bfloat162(__float2bfloat16_rn(v0 - __bfloat162float(h0)),
                                   __float2bfloat16_rn(v1 - __bfloat162float(h1)));
                *(__nv_bfloat162*)(Cl + (size_t)(r0 + 8) * ldc + col) =
                    __nv_bfloat162(__float2bfloat16_rn(v2 - __bfloat162float(h2)),
                                   __float2bfloat16_rn(v3 - __bfloat162float(h3)));
            } else {
                *(float2*)(C + (size_t)r0 * ldc + col)       = make_float2(v0, v1);
                *(float2*)(C + (size_t)(r0 + 8) * ldc + col) = make_float2(v2, v3);
            }
        }
    }
}

// ---------------------------------------------------------------------------
// fp32 -> (hi, lo) bf16, same layout (flat, vectorized by 4)
// ---------------------------------------------------------------------------
__global__ void split_rows_kernel(const float* __restrict__ in,
                                  __nv_bfloat16* __restrict__ h,
                                  __nv_bfloat16* __restrict__ l, size_t n4)
{
    size_t i = (size_t)blockIdx.x * blockDim.x + threadIdx.x;
    if (i >= n4) return;
    float4 v = ((const float4*)in)[i];
    __nv_bfloat16 hx = __float2bfloat16_rn(v.x);
    __nv_bfloat16 hy = __float2bfloat16_rn(v.y);
    __nv_bfloat16 hz = __float2bfloat16_rn(v.z);
    __nv_bfloat16 hw = __float2bfloat16_rn(v.w);
    __nv_bfloat162* h2 = (__nv_bfloat162*)h;
    __nv_bfloat162* l2 = (__nv_bfloat162*)l;
    h2[2 * i + 0] = __nv_bfloat162(hx, hy);
    h2[2 * i + 1] = __nv_bfloat162(hz, hw);
    l2[2 * i + 0] = __nv_bfloat162(__float2bfloat16_rn(v.x - __bfloat162float(hx)),
                                   __float2bfloat16_rn(v.y - __bfloat162float(hy)));
    l2[2 * i + 1] = __nv_bfloat162(__float2bfloat16_rn(v.z - __bfloat162float(hz)),
                                   __float2bfloat16_rn(v.w - __bfloat162float(hw)));
}

// ---------------------------------------------------------------------------
// fp32 [R x C] (ld=ldin) -> transposed (hi, lo) bf16 [C x R]  (weights only)
// ---------------------------------------------------------------------------
__global__ void splitT_kernel(const float* __restrict__ in, int ldin, int R,
                              __nv_bfloat16* __restrict__ h, __nv_bfloat16* __restrict__ l)
{
    __shared__ float t[32][33];
    const int c0 = blockIdx.x * 32, r0 = blockIdx.y * 32;
    #pragma unroll
    for (int j = 0; j < 4; ++j) {
        int r = r0 + threadIdx.y + j * 8;
        t[threadIdx.y + j * 8][threadIdx.x] = in[(size_t)r * ldin + c0 + threadIdx.x];
    }
    __syncthreads();
    #pragma unroll
    for (int j = 0; j < 4; ++j) {
        int c = c0 + threadIdx.y + j * 8;
        float v = t[threadIdx.x][threadIdx.y + j * 8];
        __nv_bfloat16 hv = __float2bfloat16_rn(v);
        h[(size_t)c * R + r0 + threadIdx.x] = hv;
        l[(size_t)c * R + r0 + threadIdx.x] =
            __float2bfloat16_rn(v - __bfloat162float(hv));
    }
}

// ---------------------------------------------------------------------------
// bf16-pair transpose: (h,l)[R x Cin] cols [0,Cout) -> (h,l)T [Cout x R]
// ---------------------------------------------------------------------------
__global__ void transpose_pair_kernel(const __nv_bfloat16* __restrict__ hin,
                                      const __nv_bfloat16* __restrict__ lin, int ldin,
                                      __nv_bfloat16* __restrict__ hout,
                                      __nv_bfloat16* __restrict__ lout, int ldout)
{
    __shared__ __nv_bfloat16 th[32][34];
    __shared__ __nv_bfloat16 tl[32][34];
    const int r0 = blockIdx.x * 32, c0 = blockIdx.y * 32;
    #pragma unroll
    for (int j = 0; j < 4; ++j) {
        int r = r0 + threadIdx.y + j * 8;
        th[threadIdx.y + j * 8][threadIdx.x] = hin[(size_t)r * ldin + c0 + threadIdx.x];
        tl[threadIdx.y + j * 8][threadIdx.x] = lin[(size_t)r * ldin + c0 + threadIdx.x];
    }
    __syncthreads();
    #pragma unroll
    for (int j = 0; j < 4; ++j) {
        int c = c0 + threadIdx.y + j * 8;
        hout[(size_t)c * ldout + r0 + threadIdx.x] = th[threadIdx.x][threadIdx.y + j * 8];
        lout[(size_t)c * ldout + r0 + threadIdx.x] = tl[threadIdx.x][threadIdx.y + j * 8];
    }
}

// ---------------------------------------------------------------------------
// Row softmax * adj, emitting split bf16 (hi, lo). One 512-thread block / row.
// ---------------------------------------------------------------------------
__global__ void softmax_mask_split_kernel(const float* __restrict__ S,
                                          const float* __restrict__ adj,
                                          __nv_bfloat16* __restrict__ sh,
                                          __nv_bfloat16* __restrict__ sl)
{
    __shared__ float red[16];
    const int row = blockIdx.x;
    const int tid = threadIdx.x;
    const float4* srow = (const float4*)(S + (size_t)row * NNODES);
    const float4* arow = (const float4*)(adj + (size_t)row * NNODES);

    float4 v[4];
    float m = -3.4e38f;
    #pragma unroll
    for (int i = 0; i < 4; ++i) {
        v[i] = srow[tid + i * 512];
        m = fmaxf(m, fmaxf(fmaxf(v[i].x, v[i].y), fmaxf(v[i].z, v[i].w)));
    }
    #pragma unroll
    for (int o = 16; o > 0; o >>= 1) m = fmaxf(m, __shfl_xor_sync(~0u, m, o));
    if ((tid & 31) == 0) red[tid >> 5] = m;
    __syncthreads();
    m = red[0];
    #pragma unroll
    for (int i = 1; i < 16; ++i) m = fmaxf(m, red[i]);
    __syncthreads();

    float s = 0.f;
    #pragma unroll
    for (int i = 0; i < 4; ++i) {
        v[i].x = __expf(v[i].x - m); v[i].y = __expf(v[i].y - m);
        v[i].z = __expf(v[i].z - m); v[i].w = __expf(v[i].w - m);
        s += (v[i].x + v[i].y) + (v[i].z + v[i].w);
    }
    #pragma unroll
    for (int o = 16; o > 0; o >>= 1) s += __shfl_xor_sync(~0u, s, o);
    if ((tid & 31) == 0) red[tid >> 5] = s;
    __syncthreads();
    s = red[0];
    #pragma unroll
    for (int i = 1; i < 16; ++i) s += red[i];

    const float inv = 1.0f / s;
    __nv_bfloat162* h2 = (__nv_bfloat162*)(sh + (size_t)row * NNODES);
    __nv_bfloat162* l2 = (__nv_bfloat162*)(sl + (size_t)row * NNODES);
    #pragma unroll
    for (int i = 0; i < 4; ++i) {
        float4 a = arow[tid + i * 512];
        float4 p;
        p.x = v[i].x * inv * a.x; p.y = v[i].y * inv * a.y;
        p.z = v[i].z * inv * a.z; p.w = v[i].w * inv * a.w;
        __nv_bfloat16 hx = __float2bfloat16_rn(p.x);
        __nv_bfloat16 hy = __float2bfloat16_rn(p.y);
        __nv_bfloat16 hz = __float2bfloat16_rn(p.z);
        __nv_bfloat16 hw = __float2bfloat16_rn(p.w);
        int idx = tid + i * 512;
        h2[2 * idx + 0] = __nv_bfloat162(hx, hy);
        h2[2 * idx + 1] = __nv_bfloat162(hz, hw);
        l2[2 * idx + 0] = __nv_bfloat162(__float2bfloat16_rn(p.x - __bfloat162float(hx)),
                                         __float2bfloat16_rn(p.y - __bfloat162float(hy)));
        l2[2 * idx + 1] = __nv_bfloat162(__float2bfloat16_rn(p.z - __bfloat162float(hz)),
                                         __float2bfloat16_rn(p.w - __bfloat162float(hw)));
    }
}

// ---------------------------------------------------------------------------
extern "C" void kernel_launch(void* const* d_in, const int* in_sizes, int n_in,
                              void* d_out, int out_size)
{
    const float* x0  = (const float*)d_in[0];  // [8192, 512]
    const float* adj = (const float*)d_in[1];  // [8192, 8192]
    const float* Wst = (const float*)d_in[2];  // [2, 512, 1024]
    float* out = (float*)d_out;

    cudaFuncSetAttribute(gemm_mma<0>, cudaFuncAttributeMaxDynamicSharedMemorySize, GEMM_SMEM);
    cudaFuncSetAttribute(gemm_mma<1>, cudaFuncAttributeMaxDynamicSharedMemorySize, GEMM_SMEM);
    cudaFuncSetAttribute(gemm_mma<2>, cudaFuncAttributeMaxDynamicSharedMemorySize, GEMM_SMEM);

    float *scores, *xbuf;
    __nv_bfloat16 *projh, *projl, *sh, *sl, *whTh, *whTl, *xh, *xl, *wth, *wtl;
    cudaGetSymbolAddress((void**)&scores, g_scores);
    cudaGetSymbolAddress((void**)&xbuf,   g_xbuf);
    cudaGetSymbolAddress((void**)&projh,  g_projh);
    cudaGetSymbolAddress((void**)&projl,  g_projl);
    cudaGetSymbolAddress((void**)&sh,     g_sh);
    cudaGetSymbolAddress((void**)&sl,     g_sl);
    cudaGetSymbolAddress((void**)&whTh,   g_whTh);
    cudaGetSymbolAddress((void**)&whTl,   g_whTl);
    cudaGetSymbolAddress((void**)&xh,     g_xh);
    cudaGetSymbolAddress((void**)&xl,     g_xl);
    cudaGetSymbolAddress((void**)&wth,    g_wth);
    cudaGetSymbolAddress((void**)&wtl,    g_wtl);

    for (int l = 0; l < NLAYER; ++l) {
        const float* xin  = l ? xbuf : x0;
        float*       xout = l ? out  : xbuf;
        const float* W = Wst + (size_t)l * DIM * (2 * DIM);

        // x -> split bf16
        {
            size_t n4 = (size_t)NNODES * DIM / 4;
            split_rows_kernel<<<(unsigned)((n4 + 255) / 256), 256>>>(xin, xh, xl, n4);
        }
        // W -> transposed split bf16
        splitT_kernel<<<dim3(2 * DIM / 32, DIM / 32), dim3(32, 8)>>>(W, 2 * DIM, DIM, wth, wtl);

        // G1: proj = x @ W, written directly as split bf16 pair
        gemm_mma<2><<<dim3(2 * DIM / 128, NNODES / 128), 128, GEMM_SMEM>>>(
            xh, xl, DIM, wth, wtl, DIM,
            nullptr, projh, projl, 2 * DIM, nullptr, 0, DIM);

        // Wh^T pair for the AV gemm B operand [512, 8192]
        transpose_pair_kernel<<<dim3(NNODES / 32, DIM / 32), dim3(32, 8)>>>(
            projh, projl, 2 * DIM, whTh, whTl, NNODES);

        // G2: scores = Wh @ Ws^T (fp32 out)
        gemm_mma<0><<<dim3(NNODES / 128, NNODES / 128), 128, GEMM_SMEM>>>(
            projh, projl, 2 * DIM, projh + DIM, projl + DIM, 2 * DIM,
            scores, nullptr, nullptr, NNODES, nullptr, 0, DIM);

        // softmax * adj -> split bf16
        softmax_mask_split_kernel<<<NNODES, 512>>>(scores, adj, sh, sl);

        // G3: xout = leaky(S @ Wh + xin)
        gemm_mma<1><<<dim3(DIM / 128, NNODES / 128), 128, GEMM_SMEM>>>(
            sh, sl, NNODES, whTh, whTl, NNODES,
            xout, nullptr, nullptr, DIM, xin, DIM, NNODES);
    }
}

// round 15
// speedup vs baseline: 1.1175x; 1.1039x over previous
#include <cuda_runtime.h>
#include <cuda_bf16.h>
#include <cstdint>

#define NNODES 8192
#define DIM    512
#define NLAYER 2
#define SLOPE  0.01f

// ---------------------------------------------------------------------------
// Scratch (device globals; allocation-free per harness rules)
// ---------------------------------------------------------------------------
__device__ __align__(256) float g_scores[(size_t)NNODES * NNODES];   // 256 MB
__device__ __align__(256) float g_xbuf[NNODES * DIM];                // 16 MB
__device__ __align__(256) __nv_bfloat16 g_projh[NNODES * 2 * DIM];
__device__ __align__(256) __nv_bfloat16 g_projl[NNODES * 2 * DIM];
__device__ __align__(256) __nv_bfloat16 g_sh[(size_t)NNODES * NNODES]; // 128 MB
__device__ __align__(256) __nv_bfloat16 g_sl[(size_t)NNODES * NNODES]; // 128 MB
__device__ __align__(256) __nv_bfloat16 g_whTh[DIM * NNODES];
__device__ __align__(256) __nv_bfloat16 g_whTl[DIM * NNODES];
__device__ __align__(256) __nv_bfloat16 g_xh[NNODES * DIM];
__device__ __align__(256) __nv_bfloat16 g_xl[NNODES * DIM];
__device__ __align__(256) __nv_bfloat16 g_wth[2 * DIM * DIM];
__device__ __align__(256) __nv_bfloat16 g_wtl[2 * DIM * DIM];

// ---------------------------------------------------------------------------
// Portable PTX helpers (valid on base compute_103 target)
// ---------------------------------------------------------------------------
__device__ __forceinline__ uint32_t smem_u32(const void* p) {
    uint32_t a;
    asm("{ .reg .u64 t; cvta.to.shared.u64 t, %1; cvt.u32.u64 %0, t; }" : "=r"(a) : "l"(p));
    return a;
}
__device__ __forceinline__ uint32_t swz(uint32_t off) {
    return off ^ ((off >> 3) & 0x70);
}
__device__ __forceinline__ void cp16(uint32_t dst, const void* src) {
    asm volatile("cp.async.cg.shared.global [%0], [%1], 16;" :: "r"(dst), "l"(src));
}
__device__ __forceinline__ void ldm4(uint32_t addr, uint32_t r[4]) {
    asm volatile("ldmatrix.sync.aligned.m8n8.x4.shared.b16 {%0,%1,%2,%3}, [%4];"
                 : "=r"(r[0]), "=r"(r[1]), "=r"(r[2]), "=r"(r[3]) : "r"(addr));
}
__device__ __forceinline__ void mma_bf16(float* c, const uint32_t a[4],
                                         uint32_t b0, uint32_t b1) {
    asm volatile(
        "mma.sync.aligned.m16n8k16.row.col.f32.bf16.bf16.f32 "
        "{%0,%1,%2,%3}, {%4,%5,%6,%7}, {%8,%9}, {%0,%1,%2,%3};"
        : "+f"(c[0]), "+f"(c[1]), "+f"(c[2]), "+f"(c[3])
        : "r"(a[0]), "r"(a[1]), "r"(a[2]), "r"(a[3]), "r"(b0), "r"(b1));
}

// ---------------------------------------------------------------------------
// Split-bf16 HMMA GEMM: C[M,N](fp32) = (Ah+Al)[M,K] @ (Bh+Bl)[N,K]^T
// (drops Al*Bl). CTA tile 128x128, BK=32, cp.async TRIPLE buffer.
// 128 threads, 4 warps in 2x2 grid, warp tile 64x64.
// MODE 0: C fp32.  MODE 1: C = leaky_relu(acc + resid) fp32.
// MODE 2: C written as split bf16 pair (Ch, Cl).
// ---------------------------------------------------------------------------
#define STAGE_BYTES 32768            // Ah 8K | Al 8K | Bh 8K | Bl 8K
#define GEMM_SMEM   (3 * STAGE_BYTES)

template <int MODE>
__global__ __launch_bounds__(128, 2)
void gemm_mma(const __nv_bfloat16* __restrict__ Ah, const __nv_bfloat16* __restrict__ Al,
              int lda,
              const __nv_bfloat16* __restrict__ Bh, const __nv_bfloat16* __restrict__ Bl,
              int ldb,
              float* __restrict__ C,
              __nv_bfloat16* __restrict__ Ch, __nv_bfloat16* __restrict__ Cl,
              int ldc,
              const float* __restrict__ resid, int ldr, int K)
{
    extern __shared__ __align__(1024) char smch[];
    const uint32_t smb = smem_u32(smch);
    const int tid  = threadIdx.x;
    const int lane = tid & 31;
    const int wid  = tid >> 5;
    const int wm   = wid >> 1;      // 0..1 -> 64-row slab
    const int wn   = wid & 1;       // 0..1 -> 64-col slab
    const int bm = blockIdx.y * 128;
    const int bn = blockIdx.x * 128;

    const __nv_bfloat16* srcs[4] = {
        Ah + (size_t)bm * lda, Al + (size_t)bm * lda,
        Bh + (size_t)bn * ldb, Bl + (size_t)bn * ldb };

    // cp.async: per array 512 16B chunks; 128 threads -> 4 per thread per array
    const int row0 = tid >> 2;             // 0..31
    const int seg  = tid & 3;              // 16B segment (8 bf16)
    uint32_t soff[4];
    #pragma unroll
    for (int j = 0; j < 4; ++j)
        soff[j] = swz((uint32_t)(((row0 + j * 32) << 6) | (seg << 4)));

    float acc[4][8][4];
    #pragma unroll
    for (int i = 0; i < 4; ++i)
        #pragma unroll
        for (int j = 0; j < 8; ++j)
            #pragma unroll
            for (int k = 0; k < 4; ++k) acc[i][j][k] = 0.f;

    // ldmatrix per-lane base byte offsets (unswizzled)
    const uint32_t a_base =
        (uint32_t)((wm * 64 + (lane & 15)) << 6) + ((lane >> 4) << 4);
    const uint32_t b_base =
        (uint32_t)((wn * 64 + (lane & 7) + ((lane >> 4) << 3)) << 6) + (((lane >> 3) & 1) << 4);

    const int T = K >> 5;   // BK=32 chunks (always >= 16 here)

    auto load_stage = [&](int stg, int kt) {
        const uint32_t sb = smb + stg * STAGE_BYTES;
        #pragma unroll
        for (int h = 0; h < 4; ++h) {
            const int ld = (h < 2) ? lda : ldb;
            const __nv_bfloat16* base = srcs[h] + kt + seg * 8;
            #pragma unroll
            for (int j = 0; j < 4; ++j)
                cp16(sb + h * 8192 + soff[j], base + (size_t)(row0 + j * 32) * ld);
        }
        asm volatile("cp.async.commit_group;");
    };

    // Prologue: fill 3 stages
    load_stage(0, 0);
    load_stage(1, 1 << 5);
    load_stage(2, 2 << 5);

    int cur = 0;   // stage index = t % 3; load target for t+3 is the same stage
    for (int t = 0; t < T; ++t) {
        // Ensure stage `cur` (chunk t) is resident.
        // Pending groups before wait = min(T, t+3) - t; keep at most (T-1-t, capped 2).
        const int rem = T - 1 - t;
        if (rem >= 2)      asm volatile("cp.async.wait_group 2;");
        else if (rem == 1) asm volatile("cp.async.wait_group 1;");
        else               asm volatile("cp.async.wait_group 0;");
        __syncthreads();

        const uint32_t sb = smb + cur * STAGE_BYTES;
        #pragma unroll
        for (int kk = 0; kk < 2; ++kk) {          // two k16 steps
            const uint32_t kb = kk * 32;
            uint32_t bh[4][4], bl[4][4], af[4][4];
            #pragma unroll
            for (int p = 0; p < 4; ++p)
                ldm4(sb + 16384 + swz(b_base + p * 1024 + kb), bh[p]);
            #pragma unroll
            for (int p = 0; p < 4; ++p)
                ldm4(sb + 24576 + swz(b_base + p * 1024 + kb), bl[p]);
            #pragma unroll
            for (int i = 0; i < 4; ++i)
                ldm4(sb + swz(a_base + i * 1024 + kb), af[i]);

            // Ah*Bh
            #pragma unroll
            for (int i = 0; i < 4; ++i)
                #pragma unroll
                for (int p = 0; p < 4; ++p) {
                    mma_bf16(acc[i][2 * p + 0], af[i], bh[p][0], bh[p][1]);
                    mma_bf16(acc[i][2 * p + 1], af[i], bh[p][2], bh[p][3]);
                }
            // Ah*Bl
            #pragma unroll
            for (int i = 0; i < 4; ++i)
                #pragma unroll
                for (int p = 0; p < 4; ++p) {
                    mma_bf16(acc[i][2 * p + 0], af[i], bl[p][0], bl[p][1]);
                    mma_bf16(acc[i][2 * p + 1], af[i], bl[p][2], bl[p][3]);
                }
            // Al (overwrite af) * Bh
            #pragma unroll
            for (int i = 0; i < 4; ++i)
                ldm4(sb + 8192 + swz(a_base + i * 1024 + kb), af[i]);
            #pragma unroll
            for (int i = 0; i < 4; ++i)
                #pragma unroll
                for (int p = 0; p < 4; ++p) {
                    mma_bf16(acc[i][2 * p + 0], af[i], bh[p][0], bh[p][1]);
                    mma_bf16(acc[i][2 * p + 1], af[i], bh[p][2], bh[p][3]);
                }
        }
        __syncthreads();

        // Refill the stage just consumed with chunk t+3
        if (t + 3 < T) load_stage(cur, (t + 3) << 5);
        cur = (cur == 2) ? 0 : cur + 1;
    }

    // ---- epilogue ----
    #pragma unroll
    for (int i = 0; i < 4; ++i) {
        const int r0 = bm + wm * 64 + i * 16 + (lane >> 2);
        #pragma unroll
        for (int j = 0; j < 8; ++j) {
            const int col = bn + wn * 64 + j * 8 + (lane & 3) * 2;
            float v0 = acc[i][j][0], v1 = acc[i][j][1];
            float v2 = acc[i][j][2], v3 = acc[i][j][3];
            if (MODE == 1) {
                const float* rp0 = resid + (size_t)r0 * ldr + col;
                const float* rp1 = resid + (size_t)(r0 + 8) * ldr + col;
                v0 += rp0[0]; v1 += rp0[1];
                v2 += rp1[0]; v3 += rp1[1];
                v0 = v0 >= 0.f ? v0 : SLOPE * v0;
                v1 = v1 >= 0.f ? v1 : SLOPE * v1;
                v2 = v2 >= 0.f ? v2 : SLOPE * v2;
                v3 = v3 >= 0.f ? v3 : SLOPE * v3;
            }
            if (MODE == 2) {
                __nv_bfloat16 h0 = __float2bfloat16_rn(v0);
                __nv_bfloat16 h1 = __float2bfloat16_rn(v1);
                __nv_bfloat16 h2 = __float2bfloat16_rn(v2);
                __nv_bfloat16 h3 = __float2bfloat16_rn(v3);
                *(__nv_bfloat162*)(Ch + (size_t)r0 * ldc + col) = __nv_bfloat162(h0, h1);
                *(__nv_bfloat162*)(Ch + (size_t)(r0 + 8) * ldc + col) = __nv_bfloat162(h2, h3);
                *(__nv_bfloat162*)(Cl + (size_t)r0 * ldc + col) =
                    __nv_bfloat162(__float2bfloat16_rn(v0 - __bfloat162float(h0)),
                                   __float2bfloat16_rn(v1 - __bfloat162float(h1)));
                *(__nv_bfloat162*)(Cl + (size_t)(r0 + 8) * ldc + col) =
                    __nv_bfloat162(__float2bfloat16_rn(v2 - __bfloat162float(h2)),
                                   __float2bfloat16_rn(v3 - __bfloat162float(h3)));
            } else {
                *(float2*)(C + (size_t)r0 * ldc + col)       = make_float2(v0, v1);
                *(float2*)(C + (size_t)(r0 + 8) * ldc + col) = make_float2(v2, v3);
            }
        }
    }
}

// ---------------------------------------------------------------------------
// fp32 -> (hi, lo) bf16, same layout (flat, vectorized by 4)
// ---------------------------------------------------------------------------
__global__ void split_rows_kernel(const float* __restrict__ in,
                                  __nv_bfloat16* __restrict__ h,
                                  __nv_bfloat16* __restrict__ l, size_t n4)
{
    size_t i = (size_t)blockIdx.x * blockDim.x + threadIdx.x;
    if (i >= n4) return;
    float4 v = ((const float4*)in)[i];
    __nv_bfloat16 hx = __float2bfloat16_rn(v.x);
    __nv_bfloat16 hy = __float2bfloat16_rn(v.y);
    __nv_bfloat16 hz = __float2bfloat16_rn(v.z);
    __nv_bfloat16 hw = __float2bfloat16_rn(v.w);
    __nv_bfloat162* h2 = (__nv_bfloat162*)h;
    __nv_bfloat162* l2 = (__nv_bfloat162*)l;
    h2[2 * i + 0] = __nv_bfloat162(hx, hy);
    h2[2 * i + 1] = __nv_bfloat162(hz, hw);
    l2[2 * i + 0] = __nv_bfloat162(__float2bfloat16_rn(v.x - __bfloat162float(hx)),
                                   __float2bfloat16_rn(v.y - __bfloat162float(hy)));
    l2[2 * i + 1] = __nv_bfloat162(__float2bfloat16_rn(v.z - __bfloat162float(hz)),
                                   __float2bfloat16_rn(v.w - __bfloat162float(hw)));
}

// ---------------------------------------------------------------------------
// fp32 [R x C] (ld=ldin) -> transposed (hi, lo) bf16 [C x R]  (weights only)
// ---------------------------------------------------------------------------
__global__ void splitT_kernel(const float* __restrict__ in, int ldin, int R,
                              __nv_bfloat16* __restrict__ h, __nv_bfloat16* __restrict__ l)
{
    __shared__ float t[32][33];
    const int c0 = blockIdx.x * 32, r0 = blockIdx.y * 32;
    #pragma unroll
    for (int j = 0; j < 4; ++j) {
        int r = r0 + threadIdx.y + j * 8;
        t[threadIdx.y + j * 8][threadIdx.x] = in[(size_t)r * ldin + c0 + threadIdx.x];
    }
    __syncthreads();
    #pragma unroll
    for (int j = 0; j < 4; ++j) {
        int c = c0 + threadIdx.y + j * 8;
        float v = t[threadIdx.x][threadIdx.y + j * 8];
        __nv_bfloat16 hv = __float2bfloat16_rn(v);
        h[(size_t)c * R + r0 + threadIdx.x] = hv;
        l[(size_t)c * R + r0 + threadIdx.x] =
            __float2bfloat16_rn(v - __bfloat162float(hv));
    }
}

// ---------------------------------------------------------------------------
// bf16-pair transpose: (h,l)[R x Cin] cols [0,Cout) -> (h,l)T [Cout x R]
// ---------------------------------------------------------------------------
__global__ void transpose_pair_kernel(const __nv_bfloat16* __restrict__ hin,
                                      const __nv_bfloat16* __restrict__ lin, int ldin,
                                      __nv_bfloat16* __restrict__ hout,
                                      __nv_bfloat16* __restrict__ lout, int ldout)
{
    __shared__ __nv_bfloat16 th[32][34];
    __shared__ __nv_bfloat16 tl[32][34];
    const int r0 = blockIdx.x * 32, c0 = blockIdx.y * 32;
    #pragma unroll
    for (int j = 0; j < 4; ++j) {
        int r = r0 + threadIdx.y + j * 8;
        th[threadIdx.y + j * 8][threadIdx.x] = hin[(size_t)r * ldin + c0 + threadIdx.x];
        tl[threadIdx.y + j * 8][threadIdx.x] = lin[(size_t)r * ldin + c0 + threadIdx.x];
    }
    __syncthreads();
    #pragma unroll
    for (int j = 0; j < 4; ++j) {
        int c = c0 + threadIdx.y + j * 8;
        hout[(size_t)c * ldout + r0 + threadIdx.x] = th[threadIdx.x][threadIdx.y + j * 8];
        lout[(size_t)c * ldout + r0 + threadIdx.x] = tl[threadIdx.x][threadIdx.y + j * 8];
    }
}

// ---------------------------------------------------------------------------
// Row softmax * adj, emitting split bf16 (hi, lo). One 512-thread block / row.
// ---------------------------------------------------------------------------
__global__ void softmax_mask_split_kernel(const float* __restrict__ S,
                                          const float* __restrict__ adj,
                                          __nv_bfloat16* __restrict__ sh,
                                          __nv_bfloat16* __restrict__ sl)
{
    __shared__ float red[16];
    const int row = blockIdx.x;
    const int tid = threadIdx.x;
    const float4* srow = (const float4*)(S + (size_t)row * NNODES);
    const float4* arow = (const float4*)(adj + (size_t)row * NNODES);

    float4 v[4];
    float m = -3.4e38f;
    #pragma unroll
    for (int i = 0; i < 4; ++i) {
        v[i] = srow[tid + i * 512];
        m = fmaxf(m, fmaxf(fmaxf(v[i].x, v[i].y), fmaxf(v[i].z, v[i].w)));
    }
    #pragma unroll
    for (int o = 16; o > 0; o >>= 1) m = fmaxf(m, __shfl_xor_sync(~0u, m, o));
    if ((tid & 31) == 0) red[tid >> 5] = m;
    __syncthreads();
    m = red[0];
    #pragma unroll
    for (int i = 1; i < 16; ++i) m = fmaxf(m, red[i]);
    __syncthreads();

    float s = 0.f;
    #pragma unroll
    for (int i = 0; i < 4; ++i) {
        v[i].x = __expf(v[i].x - m); v[i].y = __expf(v[i].y - m);
        v[i].z = __expf(v[i].z - m); v[i].w = __expf(v[i].w - m);
        s += (v[i].x + v[i].y) + (v[i].z + v[i].w);
    }
    #pragma unroll
    for (int o = 16; o > 0; o >>= 1) s += __shfl_xor_sync(~0u, s, o);
    if ((tid & 31) == 0) red[tid >> 5] = s;
    __syncthreads();
    s = red[0];
    #pragma unroll
    for (int i = 1; i < 16; ++i) s += red[i];

    const float inv = 1.0f / s;
    __nv_bfloat162* h2 = (__nv_bfloat162*)(sh + (size_t)row * NNODES);
    __nv_bfloat162* l2 = (__nv_bfloat162*)(sl + (size_t)row * NNODES);
    #pragma unroll
    for (int i = 0; i < 4; ++i) {
        float4 a = arow[tid + i * 512];
        float4 p;
        p.x = v[i].x * inv * a.x; p.y = v[i].y * inv * a.y;
        p.z = v[i].z * inv * a.z; p.w = v[i].w * inv * a.w;
        __nv_bfloat16 hx = __float2bfloat16_rn(p.x);
        __nv_bfloat16 hy = __float2bfloat16_rn(p.y);
        __nv_bfloat16 hz = __float2bfloat16_rn(p.z);
        __nv_bfloat16 hw = __float2bfloat16_rn(p.w);
        int idx = tid + i * 512;
        h2[2 * idx + 0] = __nv_bfloat162(hx, hy);
        h2[2 * idx + 1] = __nv_bfloat162(hz, hw);
        l2[2 * idx + 0] = __nv_bfloat162(__float2bfloat16_rn(p.x - __bfloat162float(hx)),
                                         __float2bfloat16_rn(p.y - __bfloat162float(hy)));
        l2[2 * idx + 1] = __nv_bfloat162(__float2bfloat16_rn(p.z - __bfloat162float(hz)),
                                         __float2bfloat16_rn(p.w - __bfloat162float(hw)));
    }
}

// ---------------------------------------------------------------------------
extern "C" void kernel_launch(void* const* d_in, const int* in_sizes, int n_in,
                              void* d_out, int out_size)
{
    const float* x0  = (const float*)d_in[0];  // [8192, 512]
    const float* adj = (const float*)d_in[1];  // [8192, 8192]
    const float* Wst = (const float*)d_in[2];  // [2, 512, 1024]
    float* out = (float*)d_out;

    cudaFuncSetAttribute(gemm_mma<0>, cudaFuncAttributeMaxDynamicSharedMemorySize, GEMM_SMEM);
    cudaFuncSetAttribute(gemm_mma<1>, cudaFuncAttributeMaxDynamicSharedMemorySize, GEMM_SMEM);
    cudaFuncSetAttribute(gemm_mma<2>, cudaFuncAttributeMaxDynamicSharedMemorySize, GEMM_SMEM);

    float *scores, *xbuf;
    __nv_bfloat16 *projh, *projl, *sh, *sl, *whTh, *whTl, *xh, *xl, *wth, *wtl;
    cudaGetSymbolAddress((void**)&scores, g_scores);
    cudaGetSymbolAddress((void**)&xbuf,   g_xbuf);
    cudaGetSymbolAddress((void**)&projh,  g_projh);
    cudaGetSymbolAddress((void**)&projl,  g_projl);
    cudaGetSymbolAddress((void**)&sh,     g_sh);
    cudaGetSymbolAddress((void**)&sl,     g_sl);
    cudaGetSymbolAddress((void**)&whTh,   g_whTh);
    cudaGetSymbolAddress((void**)&whTl,   g_whTl);
    cudaGetSymbolAddress((void**)&xh,     g_xh);
    cudaGetSymbolAddress((void**)&xl,     g_xl);
    cudaGetSymbolAddress((void**)&wth,    g_wth);
    cudaGetSymbolAddress((void**)&wtl,    g_wtl);

    for (int l = 0; l < NLAYER; ++l) {
        const float* xin  = l ? xbuf : x0;
        float*       xout = l ? out  : xbuf;
        const float* W = Wst + (size_t)l * DIM * (2 * DIM);

        // x -> split bf16
        {
            size_t n4 = (size_t)NNODES * DIM / 4;
            split_rows_kernel<<<(unsigned)((n4 + 255) / 256), 256>>>(xin, xh, xl, n4);
        }
        // W -> transposed split bf16
        splitT_kernel<<<dim3(2 * DIM / 32, DIM / 32), dim3(32, 8)>>>(W, 2 * DIM, DIM, wth, wtl);

        // G1: proj = x @ W, written directly as split bf16 pair
        gemm_mma<2><<<dim3(2 * DIM / 128, NNODES / 128), 128, GEMM_SMEM>>>(
            xh, xl, DIM, wth, wtl, DIM,
            nullptr, projh, projl, 2 * DIM, nullptr, 0, DIM);

        // Wh^T pair for the AV gemm B operand [512, 8192]
        transpose_pair_kernel<<<dim3(NNODES / 32, DIM / 32), dim3(32, 8)>>>(
            projh, projl, 2 * DIM, whTh, whTl, NNODES);

        // G2: scores = Wh @ Ws^T (fp32 out)
        gemm_mma<0><<<dim3(NNODES / 128, NNODES / 128), 128, GEMM_SMEM>>>(
            projh, projl, 2 * DIM, projh + DIM, projl + DIM, 2 * DIM,
            scores, nullptr, nullptr, NNODES, nullptr, 0, DIM);

        // softmax * adj -> split bf16
        softmax_mask_split_kernel<<<NNODES, 512>>>(scores, adj, sh, sl);

        // G3: xout = leaky(S @ Wh + xin)
        gemm_mma<1><<<dim3(DIM / 128, NNODES / 128), 128, GEMM_SMEM>>>(
            sh, sl, NNODES, whTh, whTl, NNODES,
            xout, nullptr, nullptr, DIM, xin, DIM, NNODES);
    }
}